// round 14
// baseline (speedup 1.0000x reference)
#include <cuda_runtime.h>
#include <cuda_bf16.h>
#include <math.h>
#include <cstdint>

// ---------------------------------------------------------------------------
// Heterogeneous fat kernel: two block types on disjoint column ranges.
//  - MMA blocks (R12 path): band-aligned Toeplitz GEMM on mma.sync, bf16
//    hi/lo split, cols [0, 36864).  576 blocks (288 tiles x 2 row halves).
//  - FIR blocks (R4 path): 80-tap FIR on the fp32 pipe with fma.rn.f32x2,
//    cols [36864, 65536).  448 blocks (28 col-tiles x 16 row-quads).
//  Interleaved 9:7 per 16 consecutive blockIdx so both pipes load every SM.
// ---------------------------------------------------------------------------

#define THREADS  256
#define L_LEN    65536
#define TAPS     80
#define HALF     40

// ---- MMA-path constants (R12) ----
#define TILE_M   128
#define ROWS     32
#define SROW     264           // uint16 per X row (528B)
#define SROW2    132
#define CM       36864         // column split point (288 * 128)
#define OFF_CHI  0
#define OFF_CLO  256
#define OFF_CPH  512
#define OFF_CPL  1024
#define OFF_XHI  1536
#define OFF_XLO  (OFF_XHI + ROWS*528)
#define SM_TOTAL (OFF_XLO + ROWS*528)   // 35328 B

// ---- FIR-path constants (R4) ----
#define FTILE    1024          // columns per FIR block
#define FVOUT    8
#define FRING    10
#define FNLOG    (FTILE + TAPS)        // 1104
#define FNQUAD   (FNLOG / 4)           // 276
#define FNPHYS   (FNLOG + FNLOG/8 + 8) // 1250
#define FLASTW   (TAPS - 2 + FVOUT)    // 86
#define NFIRCOL  28            // (65536-36864)/1024

typedef unsigned long long ull;

__device__ __forceinline__ void mma_bf16(float* d, uint32_t a0, uint32_t a1,
                                         uint32_t a2, uint32_t a3,
                                         uint32_t b0, uint32_t b1) {
    asm("mma.sync.aligned.m16n8k16.row.col.f32.bf16.bf16.f32 "
        "{%0,%1,%2,%3}, {%4,%5,%6,%7}, {%8,%9}, {%0,%1,%2,%3};"
        : "+f"(d[0]), "+f"(d[1]), "+f"(d[2]), "+f"(d[3])
        : "r"(a0), "r"(a1), "r"(a2), "r"(a3), "r"(b0), "r"(b1));
}

__device__ __forceinline__ uint32_t bfpack(float a, float b) {
    uint32_t r;
    asm("cvt.rn.bf16x2.f32 %0, %1, %2;" : "=r"(r) : "f"(b), "f"(a));
    return r;
}

__device__ __forceinline__ uint16_t bfbits(__nv_bfloat16 h) {
    return *reinterpret_cast<uint16_t*>(&h);
}

// softmax(tw) probabilities
__device__ __forceinline__ void softmax4(const float* __restrict__ tw, float* p) {
    float w0 = tw[0], w1 = tw[1], w2 = tw[2], w3 = tw[3];
    float mx = fmaxf(fmaxf(w0, w1), fmaxf(w2, w3));
    float e0 = expf(w0 - mx), e1 = expf(w1 - mx);
    float e2 = expf(w2 - mx), e3 = expf(w3 - mx);
    float s  = 1.0f / (e0 + e1 + e2 + e3);
    p[0] = e0 * s; p[1] = e1 * s; p[2] = e2 * s; p[3] = e3 * s;
}

// combined Hann filter tap, zero outside [0, 80)
__device__ __forceinline__ float tap(int t, const float* p) {
    const int widths[4] = { 10, 20, 30, 40 };
    int dd = t - HALF;
    float c = 0.0f;
    #pragma unroll
    for (int i = 0; i < 4; ++i) {
        int w = widths[i], k = dd + w;
        if (k >= 0 && k < 2 * w) {
            float h = 0.5f - 0.5f * cosf(6.283185307179586f * (float)k
                                         / (float)(2 * w - 1));
            c = fmaf(p[i], h, c);
        }
    }
    return c;
}

// FIR stride-9 padded shared layout
__device__ __forceinline__ int fpad(int i) { return i + (i >> 3); }

// ===========================================================================
__global__ __launch_bounds__(THREADS, 4)
void hann_hybrid_kernel(const float* __restrict__ x, const float* __restrict__ tw,
                        float* __restrict__ out) {
    extern __shared__ __align__(16) char smem[];
    const int tid = threadIdx.x;
    const int bid = blockIdx.x;
    const int slot = bid & 15;

    if (slot < 9) {
        // ================= MMA path (R12 verbatim) =========================
        const int mb   = (bid >> 4) * 9 + slot;      // 0..575
        const int col0 = (mb >> 1) * TILE_M;         // [0, CM)
        const int rb   = (mb & 1) * ROWS;

        uint16_t* chi16 = reinterpret_cast<uint16_t*>(smem + OFF_CHI);
        uint16_t* clo16 = reinterpret_cast<uint16_t*>(smem + OFF_CLO);
        uint32_t* cph   = reinterpret_cast<uint32_t*>(smem + OFF_CPH);
        uint32_t* cpl   = reinterpret_cast<uint32_t*>(smem + OFF_CPL);
        uint16_t* xhi   = reinterpret_cast<uint16_t*>(smem + OFF_XHI);
        uint16_t* xlo   = reinterpret_cast<uint16_t*>(smem + OFF_XLO);

        if (tid < 128) { chi16[tid] = 0; clo16[tid] = 0; }

        #pragma unroll
        for (int it = 0; it < 4; ++it) {
            int idx = tid + it * THREADS;
            if (idx < ROWS * 26) {
                int row = idx / 26;
                int c8  = idx - row * 26;
                int kk  = c8 * 8;
                int g   = col0 - HALF + kk;
                const float* xr = x + (size_t)(rb + row) * L_LEN;
                float4 va, vb;
                if (g >= 0 && g + 8 <= L_LEN) {
                    va = *reinterpret_cast<const float4*>(xr + g);
                    vb = *reinterpret_cast<const float4*>(xr + g + 4);
                } else {
                    float tp[8];
                    #pragma unroll
                    for (int e = 0; e < 8; ++e) {
                        int ge = g + e;
                        tp[e] = (ge >= 0 && ge < L_LEN) ? xr[ge] : 0.0f;
                    }
                    va = make_float4(tp[0], tp[1], tp[2], tp[3]);
                    vb = make_float4(tp[4], tp[5], tp[6], tp[7]);
                }
                uint32_t h01 = bfpack(va.x, va.y), h23 = bfpack(va.z, va.w);
                uint32_t h45 = bfpack(vb.x, vb.y), h67 = bfpack(vb.z, vb.w);
                float l0 = va.x - __uint_as_float(h01 << 16);
                float l1 = va.y - __uint_as_float(h01 & 0xFFFF0000u);
                float l2 = va.z - __uint_as_float(h23 << 16);
                float l3 = va.w - __uint_as_float(h23 & 0xFFFF0000u);
                float l4 = vb.x - __uint_as_float(h45 << 16);
                float l5 = vb.y - __uint_as_float(h45 & 0xFFFF0000u);
                float l6 = vb.z - __uint_as_float(h67 << 16);
                float l7 = vb.w - __uint_as_float(h67 & 0xFFFF0000u);
                uint32_t q01 = bfpack(l0, l1), q23 = bfpack(l2, l3);
                uint32_t q45 = bfpack(l4, l5), q67 = bfpack(l6, l7);
                uint32_t eoff = row * SROW + kk;
                *reinterpret_cast<uint4*>(xhi + eoff) = make_uint4(h01, h23, h45, h67);
                *reinterpret_cast<uint4*>(xlo + eoff) = make_uint4(q01, q23, q45, q67);
            }
        }
        __syncthreads();

        if (tid < TAPS) {
            float p[4];
            softmax4(tw, p);
            float c = tap(tid, p);
            __nv_bfloat16 chh = __float2bfloat16(c);
            __nv_bfloat16 cll = __float2bfloat16(c - __bfloat162float(chh));
            chi16[tid + 24] = bfbits(chh);
            clo16[tid + 24] = bfbits(cll);
        }
        __syncthreads();

        if (tid < 112) {
            cph[tid] = (uint32_t)chi16[tid + 9] << 16 | chi16[tid + 8];
            cpl[tid] = (uint32_t)clo16[tid + 9] << 16 | clo16[tid + 8];
        }
        __syncthreads();

        const int wid = tid >> 5;
        const int lid = tid & 31;
        const int g   = lid >> 2;
        const int t   = lid & 3;
        const int wm0 = wid * 16;
        const int mg  = col0 + wm0 + g;

        float d[4][4];
        #pragma unroll
        for (int nfi = 0; nfi < 4; ++nfi)
            #pragma unroll
            for (int r = 0; r < 4; ++r) d[nfi][r] = 0.0f;

        #pragma unroll
        for (int s = 0; s < 6; ++s) {
            const int base = 16 + 16 * s + 2 * t - g;
            uint32_t ah0 = cph[base];
            uint32_t ah1 = cph[base - 8];
            uint32_t ah2 = cph[base + 8];
            uint32_t al0 = cpl[base];
            uint32_t al1 = cpl[base - 8];
            uint32_t al2 = cpl[base + 8];

            const int ki = ((wm0 + 16 * s) >> 1) + t;

            uint32_t bh0[4], bh1[4], bl0[4], bl1[4];
            #pragma unroll
            for (int nfi = 0; nfi < 4; ++nfi) {
                const int n = nfi * 8 + g;
                const uint32_t* ph = reinterpret_cast<const uint32_t*>(xhi) + n * SROW2;
                const uint32_t* pl = reinterpret_cast<const uint32_t*>(xlo) + n * SROW2;
                bh0[nfi] = ph[ki]; bh1[nfi] = ph[ki + 4];
                bl0[nfi] = pl[ki]; bl1[nfi] = pl[ki + 4];
            }
            #pragma unroll
            for (int nfi = 0; nfi < 4; ++nfi)
                mma_bf16(d[nfi], ah0, ah1, ah2, ah0, bh0[nfi], bh1[nfi]);
            #pragma unroll
            for (int nfi = 0; nfi < 4; ++nfi)
                mma_bf16(d[nfi], ah0, ah1, ah2, ah0, bl0[nfi], bl1[nfi]);
            #pragma unroll
            for (int nfi = 0; nfi < 4; ++nfi)
                mma_bf16(d[nfi], al0, al1, al2, al0, bh0[nfi], bh1[nfi]);
        }

        #pragma unroll
        for (int nfi = 0; nfi < 4; ++nfi) {
            const size_t n0 = (size_t)(rb + nfi * 8 + 2 * t) * L_LEN;
            out[n0 + mg]             = d[nfi][0];
            out[n0 + L_LEN + mg]     = d[nfi][1];
            out[n0 + mg + 8]         = d[nfi][2];
            out[n0 + L_LEN + mg + 8] = d[nfi][3];
        }
    } else {
        // ================= FIR path (R4 verbatim, 2 row-pairs/block) ========
        const int fb     = (bid >> 4) * 7 + (slot - 9);   // 0..447
        const int colblk = fb % NFIRCOL;
        const int rowq   = fb / NFIRCOL;                  // 0..15
        const int col0   = CM + colblk * FTILE;
        const int group  = tid >> 7;                      // 0 or 1
        const int tg     = tid & 127;
        const int rp     = rowq * 2 + group;              // rowpair 0..31

        float2* sc = reinterpret_cast<float2*>(smem);               // 80
        float2* sx = reinterpret_cast<float2*>(smem + 640) + group * FNPHYS;

        // tile fill: quads, LDG.128 per row of the pair
        const float* __restrict__ xa = x + (size_t)(2 * rp) * L_LEN;
        const float* __restrict__ xb = xa + L_LEN;
        #pragma unroll
        for (int it = 0; it < 3; ++it) {
            int q = tg + it * 128;
            if (q < FNQUAD) {
                int i = q * 4;
                int g = col0 - HALF + i;                  // >= 0 here (col0 >= CM)
                float4 a = make_float4(0.f, 0.f, 0.f, 0.f);
                float4 b = make_float4(0.f, 0.f, 0.f, 0.f);
                if (g + 3 < L_LEN) {
                    a = *reinterpret_cast<const float4*>(xa + g);
                    b = *reinterpret_cast<const float4*>(xb + g);
                }
                int ph = fpad(i);
                sx[ph    ] = make_float2(a.x, b.x);
                sx[ph + 1] = make_float2(a.y, b.y);
                sx[ph + 2] = make_float2(a.z, b.z);
                sx[ph + 3] = make_float2(a.w, b.w);
            }
        }

        // coefficients (threads 0..79 of the block) overlap fill latency
        if (tid < TAPS) {
            float p[4];
            softmax4(tw, p);
            float c = tap(tid, p);
            sc[tid] = make_float2(c, c);
        }
        __syncthreads();

        const ull* __restrict__ P =
            reinterpret_cast<const ull*>(sx) + 9 * tg;
        const ulonglong2* __restrict__ scq =
            reinterpret_cast<const ulonglong2*>(sc);

        ull acc[FVOUT];
        ull win[FRING];
        #pragma unroll
        for (int v = 0; v < FVOUT; ++v) acc[v] = 0ull;
        #pragma unroll
        for (int j = 0; j < FRING; ++j) win[j] = P[fpad(j)];

        #pragma unroll
        for (int t = 0; t < TAPS; t += 2) {
            ulonglong2 cq = scq[t >> 1];
            #pragma unroll
            for (int v = 0; v < FVOUT; ++v)
                asm("fma.rn.f32x2 %0, %1, %2, %0;"
                    : "+l"(acc[v]) : "l"(win[(t + v) % FRING]), "l"(cq.x));
            if (t + FRING <= FLASTW)
                win[t % FRING] = P[fpad(t + FRING)];
            #pragma unroll
            for (int v = 0; v < FVOUT; ++v)
                asm("fma.rn.f32x2 %0, %1, %2, %0;"
                    : "+l"(acc[v]) : "l"(win[(t + 1 + v) % FRING]), "l"(cq.y));
            if (t + 1 + FRING <= FLASTW)
                win[(t + 1) % FRING] = P[fpad(t + 1 + FRING)];
        }

        float* oa = out + (size_t)(2 * rp)     * L_LEN + col0 + tg * FVOUT;
        float* ob = out + (size_t)(2 * rp + 1) * L_LEN + col0 + tg * FVOUT;
        #pragma unroll
        for (int v = 0; v < FVOUT; v += 4) {
            float4 qa, qb;
            asm("mov.b64 {%0, %1}, %2;" : "=f"(qa.x), "=f"(qb.x) : "l"(acc[v]));
            asm("mov.b64 {%0, %1}, %2;" : "=f"(qa.y), "=f"(qb.y) : "l"(acc[v+1]));
            asm("mov.b64 {%0, %1}, %2;" : "=f"(qa.z), "=f"(qb.z) : "l"(acc[v+2]));
            asm("mov.b64 {%0, %1}, %2;" : "=f"(qa.w), "=f"(qb.w) : "l"(acc[v+3]));
            *reinterpret_cast<float4*>(oa + v) = qa;
            *reinterpret_cast<float4*>(ob + v) = qb;
        }
    }
}

extern "C" void kernel_launch(void* const* d_in, const int* in_sizes, int n_in,
                              void* d_out, int out_size) {
    const float* x  = (const float*)d_in[0];   // [64, 65536] fp32
    const float* tw = (const float*)d_in[1];   // [4] fp32
    float* out = (float*)d_out;

    cudaFuncSetAttribute(hann_hybrid_kernel,
                         cudaFuncAttributeMaxDynamicSharedMemorySize, SM_TOTAL);
    hann_hybrid_kernel<<<1024, THREADS, SM_TOTAL>>>(x, tw, out);
}

// round 15
// speedup vs baseline: 1.1062x; 1.1062x over previous
#include <cuda_runtime.h>
#include <cuda_bf16.h>
#include <math.h>
#include <cstdint>

// ---------------------------------------------------------------------------
// HanningTemplateLayer as band-aligned Toeplitz GEMM on mma.sync (bf16 hi/lo).
// Persistent column-CTA: each CTA owns a 128-col tile and loops over both
// 32-row batch halves.  grid = 512 -> exactly one wave at 4 CTAs/SM.
//   D[m,n] = sum_k T[m,k] * X[n,k];  T[m,k] = c[k-m];  X[n,k] = x[rb+n, col0-40+k]
//   out[rb+n, col0+m] = D[m,n]
// Warp w owns m in [16w,16w+16); band spans k in [16w,16w+96): 6 k16-steps.
// 3 products: Ah*Bh + Ah*Bl + Al*Bh (fp32 accumulate), rel_err ~4e-6.
// Coeff pair tables computed once per CTA (direct parallel form).
// ---------------------------------------------------------------------------

#define THREADS 256
#define TILE_M  128
#define ROWS    32
#define TAPS    80
#define HALF    40
#define L_LEN   65536
#define SROW    264          // uint16 per X row (528B; stride mod 128 = 16)
#define SROW2   132          // uint32 stride per X row

// smem byte offsets
#define OFF_CPH   0                     // 112 x u32 hi pair table
#define OFF_CPL   512
#define OFF_XHI   1536                  // 32 rows x 528B
#define OFF_XLO   (OFF_XHI + ROWS*528)
#define SM_TOTAL  (OFF_XLO + ROWS*528)  // 35328 B

__device__ __forceinline__ void mma_bf16(float* d, uint32_t a0, uint32_t a1,
                                         uint32_t a2, uint32_t a3,
                                         uint32_t b0, uint32_t b1) {
    asm("mma.sync.aligned.m16n8k16.row.col.f32.bf16.bf16.f32 "
        "{%0,%1,%2,%3}, {%4,%5,%6,%7}, {%8,%9}, {%0,%1,%2,%3};"
        : "+f"(d[0]), "+f"(d[1]), "+f"(d[2]), "+f"(d[3])
        : "r"(a0), "r"(a1), "r"(a2), "r"(a3), "r"(b0), "r"(b1));
}

// pack two f32 -> bf16x2 {lo half: a, hi half: b}
__device__ __forceinline__ uint32_t bfpack(float a, float b) {
    uint32_t r;
    asm("cvt.rn.bf16x2.f32 %0, %1, %2;" : "=r"(r) : "f"(b), "f"(a));
    return r;
}

__device__ __forceinline__ uint16_t bfbits(__nv_bfloat16 h) {
    return *reinterpret_cast<uint16_t*>(&h);
}

// combined Hann filter tap, zero outside [0, 80)
__device__ __forceinline__ float tap(int t, const float* p) {
    const int widths[4] = { 10, 20, 30, 40 };
    int dd = t - HALF;
    float c = 0.0f;
    #pragma unroll
    for (int i = 0; i < 4; ++i) {
        int w = widths[i], k = dd + w;
        if (k >= 0 && k < 2 * w) {
            float h = 0.5f - 0.5f * cosf(6.283185307179586f * (float)k
                                         / (float)(2 * w - 1));
            c = fmaf(p[i], h, c);
        }
    }
    return c;
}

__global__ __launch_bounds__(THREADS, 4)
void hann_mma_kernel(const float* __restrict__ x, const float* __restrict__ tw,
                     float* __restrict__ out) {
    extern __shared__ __align__(16) char smem[];
    uint32_t* cph = reinterpret_cast<uint32_t*>(smem + OFF_CPH);
    uint32_t* cpl = reinterpret_cast<uint32_t*>(smem + OFF_CPL);
    uint16_t* xhi = reinterpret_cast<uint16_t*>(smem + OFF_XHI);
    uint16_t* xlo = reinterpret_cast<uint16_t*>(smem + OFF_XLO);

    const int tid  = threadIdx.x;
    const int col0 = blockIdx.x * TILE_M;

    const int wid = tid >> 5;
    const int lid = tid & 31;
    const int g   = lid >> 2;                 // group (row / n within frag)
    const int t   = lid & 3;                  // thread-in-group
    const int wm0 = wid * 16;
    const int mg  = col0 + wm0 + g;

    #pragma unroll
    for (int half = 0; half < 2; ++half) {
        const int rb = half * ROWS;

        if (half)
            __syncthreads();   // all mainloop LDS of half 0 done before refill

        // -- X tile fill: 32 rows x 26 oct-chunks; fp32 -> bf16 hi/lo ----------
        #pragma unroll
        for (int it = 0; it < 4; ++it) {
            int idx = tid + it * THREADS;            // < 1024
            if (idx < ROWS * 26) {
                int row = idx / 26;
                int c8  = idx - row * 26;
                int kk  = c8 * 8;
                int gg  = col0 - HALF + kk;          // 4-aligned
                const float* xr = x + (size_t)(rb + row) * L_LEN;
                float4 va, vb;
                if (gg >= 0 && gg + 8 <= L_LEN) {
                    va = *reinterpret_cast<const float4*>(xr + gg);
                    vb = *reinterpret_cast<const float4*>(xr + gg + 4);
                } else {
                    float tp[8];
                    #pragma unroll
                    for (int e = 0; e < 8; ++e) {
                        int ge = gg + e;
                        tp[e] = (ge >= 0 && ge < L_LEN) ? xr[ge] : 0.0f;
                    }
                    va = make_float4(tp[0], tp[1], tp[2], tp[3]);
                    vb = make_float4(tp[4], tp[5], tp[6], tp[7]);
                }
                uint32_t h01 = bfpack(va.x, va.y), h23 = bfpack(va.z, va.w);
                uint32_t h45 = bfpack(vb.x, vb.y), h67 = bfpack(vb.z, vb.w);
                float l0 = va.x - __uint_as_float(h01 << 16);
                float l1 = va.y - __uint_as_float(h01 & 0xFFFF0000u);
                float l2 = va.z - __uint_as_float(h23 << 16);
                float l3 = va.w - __uint_as_float(h23 & 0xFFFF0000u);
                float l4 = vb.x - __uint_as_float(h45 << 16);
                float l5 = vb.y - __uint_as_float(h45 & 0xFFFF0000u);
                float l6 = vb.z - __uint_as_float(h67 << 16);
                float l7 = vb.w - __uint_as_float(h67 & 0xFFFF0000u);
                uint32_t q01 = bfpack(l0, l1), q23 = bfpack(l2, l3);
                uint32_t q45 = bfpack(l4, l5), q67 = bfpack(l6, l7);
                uint32_t eoff = row * SROW + kk;     // element offset, 8-aligned
                *reinterpret_cast<uint4*>(xhi + eoff) = make_uint4(h01, h23, h45, h67);
                *reinterpret_cast<uint4*>(xlo + eoff) = make_uint4(q01, q23, q45, q67);
            }
        }

        // -- pair tables (ONCE, overlaps first fill's LDG latency) --------------
        // cp*[i] = (c(i-16), c(i-15)) as bf16 hi/lo pairs, i in [0, 112)
        if (half == 0 && tid < 112) {
            float w0 = tw[0], w1 = tw[1], w2 = tw[2], w3 = tw[3];
            float mx = fmaxf(fmaxf(w0, w1), fmaxf(w2, w3));
            float e0 = expf(w0 - mx), e1 = expf(w1 - mx);
            float e2 = expf(w2 - mx), e3 = expf(w3 - mx);
            float s  = 1.0f / (e0 + e1 + e2 + e3);
            float p[4] = { e0 * s, e1 * s, e2 * s, e3 * s };
            float ca = tap(tid - 16, p);
            float cb = tap(tid - 15, p);
            __nv_bfloat16 cah = __float2bfloat16(ca);
            __nv_bfloat16 cbh = __float2bfloat16(cb);
            __nv_bfloat16 cal = __float2bfloat16(ca - __bfloat162float(cah));
            __nv_bfloat16 cbl = __float2bfloat16(cb - __bfloat162float(cbh));
            cph[tid] = (uint32_t)bfbits(cbh) << 16 | bfbits(cah);
            cpl[tid] = (uint32_t)bfbits(cbl) << 16 | bfbits(cal);
        }
        __syncthreads();

        // -- band-aligned MMA: warp w -> m in [16w,16w+16), k in [16w,16w+96) --
        float d[4][4];
        #pragma unroll
        for (int nfi = 0; nfi < 4; ++nfi)
            #pragma unroll
            for (int r = 0; r < 4; ++r) d[nfi][r] = 0.0f;

        #pragma unroll
        for (int s = 0; s < 6; ++s) {
            // A fragments: ah3 == ah0, al3 == al0 (Toeplitz row shift)
            const int base = 16 + 16 * s + 2 * t - g;
            uint32_t ah0 = cph[base];
            uint32_t ah1 = cph[base - 8];
            uint32_t ah2 = cph[base + 8];
            uint32_t al0 = cpl[base];
            uint32_t al1 = cpl[base - 8];
            uint32_t al2 = cpl[base + 8];

            const int ki = ((wm0 + 16 * s) >> 1) + t;   // uint32 index of k+2t

            // load ALL B fragments for this k-step first
            uint32_t bh0[4], bh1[4], bl0[4], bl1[4];
            #pragma unroll
            for (int nfi = 0; nfi < 4; ++nfi) {
                const int n = nfi * 8 + g;
                const uint32_t* ph = reinterpret_cast<const uint32_t*>(xhi) + n * SROW2;
                const uint32_t* pl = reinterpret_cast<const uint32_t*>(xlo) + n * SROW2;
                bh0[nfi] = ph[ki]; bh1[nfi] = ph[ki + 4];
                bl0[nfi] = pl[ki]; bl1[nfi] = pl[ki + 4];
            }

            // product-major MMA stream: same-acc dependency distance = 4
            #pragma unroll
            for (int nfi = 0; nfi < 4; ++nfi)
                mma_bf16(d[nfi], ah0, ah1, ah2, ah0, bh0[nfi], bh1[nfi]);
            #pragma unroll
            for (int nfi = 0; nfi < 4; ++nfi)
                mma_bf16(d[nfi], ah0, ah1, ah2, ah0, bl0[nfi], bl1[nfi]);
            #pragma unroll
            for (int nfi = 0; nfi < 4; ++nfi)
                mma_bf16(d[nfi], al0, al1, al2, al0, bh0[nfi], bh1[nfi]);
        }

        // -- epilogue: D[m,n] -> out[rb + n, col0 + m] --------------------------
        #pragma unroll
        for (int nfi = 0; nfi < 4; ++nfi) {
            const size_t n0 = (size_t)(rb + nfi * 8 + 2 * t) * L_LEN;
            out[n0 + mg]             = d[nfi][0];
            out[n0 + L_LEN + mg]     = d[nfi][1];
            out[n0 + mg + 8]         = d[nfi][2];
            out[n0 + L_LEN + mg + 8] = d[nfi][3];
        }
    }
}

extern "C" void kernel_launch(void* const* d_in, const int* in_sizes, int n_in,
                              void* d_out, int out_size) {
    const float* x  = (const float*)d_in[0];   // [64, 65536] fp32
    const float* tw = (const float*)d_in[1];   // [4] fp32
    float* out = (float*)d_out;

    cudaFuncSetAttribute(hann_mma_kernel,
                         cudaFuncAttributeMaxDynamicSharedMemorySize, SM_TOTAL);
    hann_mma_kernel<<<L_LEN / TILE_M, THREADS, SM_TOTAL>>>(x, tw, out);  // 512 CTAs
}

// round 16
// speedup vs baseline: 1.1529x; 1.0422x over previous
#include <cuda_runtime.h>
#include <cuda_bf16.h>
#include <math.h>
#include <cstdint>

// ---------------------------------------------------------------------------
// HanningTemplateLayer as band-aligned Toeplitz GEMM on mma.sync (bf16 hi/lo).
// CTA = 128 output columns x 32 batch rows.  grid = (512 tiles, 2 row-halves).
//   D[m,n] = sum_k T[m,k] * X[n,k];  T[m,k] = c[k-m];  X[n,k] = x[rb+n, col0-40+k]
//   out[rb+n, col0+m] = D[m,n]
// Warp w owns m in [16w,16w+16); band spans k in [16w,16w+96): 6 k16-steps.
// 3 products: Ah*Bh + Ah*Bl + Al*Bh (fp32 accumulate), rel_err ~4e-6.
// R16 = R12 with __launch_bounds__(256, 5): regs fit (50 <= 51), so the 5th
// CTA/SM is free occupancy (32 -> 40 warps/SM), waves 1.73 -> 1.38.
// ---------------------------------------------------------------------------

#define THREADS 256
#define TILE_M  128
#define ROWS    32
#define TAPS    80
#define HALF    40
#define L_LEN   65536
#define SROW    264          // uint16 per X row (528B; stride mod 128 = 16)
#define SROW2   132          // uint32 stride per X row

// smem byte offsets
#define OFF_CHI   0                     // 128 x u16 bf16(c_hi), band at +24
#define OFF_CLO   256
#define OFF_CPH   512                   // 112 x u32 pair table
#define OFF_CPL   1024
#define OFF_XHI   1536                  // 32 rows x 528B
#define OFF_XLO   (OFF_XHI + ROWS*528)
#define SM_TOTAL  (OFF_XLO + ROWS*528)  // 35328 B

__device__ __forceinline__ void mma_bf16(float* d, uint32_t a0, uint32_t a1,
                                         uint32_t a2, uint32_t a3,
                                         uint32_t b0, uint32_t b1) {
    asm("mma.sync.aligned.m16n8k16.row.col.f32.bf16.bf16.f32 "
        "{%0,%1,%2,%3}, {%4,%5,%6,%7}, {%8,%9}, {%0,%1,%2,%3};"
        : "+f"(d[0]), "+f"(d[1]), "+f"(d[2]), "+f"(d[3])
        : "r"(a0), "r"(a1), "r"(a2), "r"(a3), "r"(b0), "r"(b1));
}

// pack two f32 -> bf16x2 {lo half: a, hi half: b}
__device__ __forceinline__ uint32_t bfpack(float a, float b) {
    uint32_t r;
    asm("cvt.rn.bf16x2.f32 %0, %1, %2;" : "=r"(r) : "f"(b), "f"(a));
    return r;
}

__device__ __forceinline__ uint16_t bfbits(__nv_bfloat16 h) {
    return *reinterpret_cast<uint16_t*>(&h);
}

__global__ __launch_bounds__(THREADS, 5)
void hann_mma_kernel(const float* __restrict__ x, const float* __restrict__ tw,
                     float* __restrict__ out) {
    extern __shared__ __align__(16) char smem[];
    uint16_t* chi16 = reinterpret_cast<uint16_t*>(smem + OFF_CHI);
    uint16_t* clo16 = reinterpret_cast<uint16_t*>(smem + OFF_CLO);
    uint32_t* cph   = reinterpret_cast<uint32_t*>(smem + OFF_CPH);
    uint32_t* cpl   = reinterpret_cast<uint32_t*>(smem + OFF_CPL);
    uint16_t* xhi   = reinterpret_cast<uint16_t*>(smem + OFF_XHI);
    uint16_t* xlo   = reinterpret_cast<uint16_t*>(smem + OFF_XLO);

    const int tid  = threadIdx.x;
    const int col0 = blockIdx.x * TILE_M;
    const int rb   = blockIdx.y * ROWS;       // batch-row base of this CTA

    // -- zero coeff scratch (band written after the barrier below) -------------
    if (tid < 128) { chi16[tid] = 0; clo16[tid] = 0; }

    // -- X tile fill: 32 rows x 26 oct-chunks; fp32 -> bf16 hi/lo (vectorized) --
    #pragma unroll
    for (int it = 0; it < 4; ++it) {
        int idx = tid + it * THREADS;            // < 1024
        if (idx < ROWS * 26) {
            int row = idx / 26;
            int c8  = idx - row * 26;
            int kk  = c8 * 8;
            int g   = col0 - HALF + kk;          // 4-aligned
            const float* xr = x + (size_t)(rb + row) * L_LEN;
            float4 va, vb;
            if (g >= 0 && g + 8 <= L_LEN) {
                va = *reinterpret_cast<const float4*>(xr + g);
                vb = *reinterpret_cast<const float4*>(xr + g + 4);
            } else {
                float tp[8];
                #pragma unroll
                for (int e = 0; e < 8; ++e) {
                    int ge = g + e;
                    tp[e] = (ge >= 0 && ge < L_LEN) ? xr[ge] : 0.0f;
                }
                va = make_float4(tp[0], tp[1], tp[2], tp[3]);
                vb = make_float4(tp[4], tp[5], tp[6], tp[7]);
            }
            uint32_t h01 = bfpack(va.x, va.y), h23 = bfpack(va.z, va.w);
            uint32_t h45 = bfpack(vb.x, vb.y), h67 = bfpack(vb.z, vb.w);
            float l0 = va.x - __uint_as_float(h01 << 16);
            float l1 = va.y - __uint_as_float(h01 & 0xFFFF0000u);
            float l2 = va.z - __uint_as_float(h23 << 16);
            float l3 = va.w - __uint_as_float(h23 & 0xFFFF0000u);
            float l4 = vb.x - __uint_as_float(h45 << 16);
            float l5 = vb.y - __uint_as_float(h45 & 0xFFFF0000u);
            float l6 = vb.z - __uint_as_float(h67 << 16);
            float l7 = vb.w - __uint_as_float(h67 & 0xFFFF0000u);
            uint32_t q01 = bfpack(l0, l1), q23 = bfpack(l2, l3);
            uint32_t q45 = bfpack(l4, l5), q67 = bfpack(l6, l7);
            uint32_t eoff = row * SROW + kk;     // element offset, 8-aligned
            *reinterpret_cast<uint4*>(xhi + eoff) = make_uint4(h01, h23, h45, h67);
            *reinterpret_cast<uint4*>(xlo + eoff) = make_uint4(q01, q23, q45, q67);
        }
    }
    __syncthreads();   // orders coeff-scratch zeroing before the band write

    // -- coefficients c[t] (threads 0..79), bf16 hi/lo -------------------------
    if (tid < TAPS) {
        float w0 = tw[0], w1 = tw[1], w2 = tw[2], w3 = tw[3];
        float mx = fmaxf(fmaxf(w0, w1), fmaxf(w2, w3));
        float e0 = expf(w0 - mx), e1 = expf(w1 - mx);
        float e2 = expf(w2 - mx), e3 = expf(w3 - mx);
        float s  = 1.0f / (e0 + e1 + e2 + e3);
        float p[4] = { e0 * s, e1 * s, e2 * s, e3 * s };
        const int widths[4] = { 10, 20, 30, 40 };
        int dd = tid - HALF;
        float c = 0.0f;
        #pragma unroll
        for (int i = 0; i < 4; ++i) {
            int w = widths[i], k = dd + w;
            if (k >= 0 && k < 2 * w) {
                float h = 0.5f - 0.5f * cosf(6.283185307179586f * (float)k
                                             / (float)(2 * w - 1));
                c = fmaf(p[i], h, c);
            }
        }
        __nv_bfloat16 chh = __float2bfloat16(c);
        __nv_bfloat16 cll = __float2bfloat16(c - __bfloat162float(chh));
        chi16[tid + 24] = bfbits(chh);
        clo16[tid + 24] = bfbits(cll);
    }
    __syncthreads();

    // -- pair tables: cpair[16 + d] = (c[d], c[d+1]), d in [-16, 96) -----------
    if (tid < 112) {
        cph[tid] = (uint32_t)chi16[tid + 9] << 16 | chi16[tid + 8];
        cpl[tid] = (uint32_t)clo16[tid + 9] << 16 | clo16[tid + 8];
    }
    __syncthreads();

    // -- band-aligned MMA: warp w -> m in [16w,16w+16), k in [16w,16w+96) ------
    const int wid = tid >> 5;
    const int lid = tid & 31;
    const int g   = lid >> 2;                 // group (row / n within frag)
    const int t   = lid & 3;                  // thread-in-group
    const int wm0 = wid * 16;
    const int mg  = col0 + wm0 + g;

    float d[4][4];
    #pragma unroll
    for (int nfi = 0; nfi < 4; ++nfi)
        #pragma unroll
        for (int r = 0; r < 4; ++r) d[nfi][r] = 0.0f;

    #pragma unroll
    for (int s = 0; s < 6; ++s) {
        // A fragments: ah3 == ah0, al3 == al0 (Toeplitz row shift)
        const int base = 16 + 16 * s + 2 * t - g;
        uint32_t ah0 = cph[base];
        uint32_t ah1 = cph[base - 8];
        uint32_t ah2 = cph[base + 8];
        uint32_t al0 = cpl[base];
        uint32_t al1 = cpl[base - 8];
        uint32_t al2 = cpl[base + 8];

        const int ki = ((wm0 + 16 * s) >> 1) + t;   // uint32 index of k+2t

        // load ALL B fragments for this k-step first
        uint32_t bh0[4], bh1[4], bl0[4], bl1[4];
        #pragma unroll
        for (int nfi = 0; nfi < 4; ++nfi) {
            const int n = nfi * 8 + g;
            const uint32_t* ph = reinterpret_cast<const uint32_t*>(xhi) + n * SROW2;
            const uint32_t* pl = reinterpret_cast<const uint32_t*>(xlo) + n * SROW2;
            bh0[nfi] = ph[ki]; bh1[nfi] = ph[ki + 4];
            bl0[nfi] = pl[ki]; bl1[nfi] = pl[ki + 4];
        }

        // product-major MMA stream: same-acc dependency distance = 4
        #pragma unroll
        for (int nfi = 0; nfi < 4; ++nfi)
            mma_bf16(d[nfi], ah0, ah1, ah2, ah0, bh0[nfi], bh1[nfi]);
        #pragma unroll
        for (int nfi = 0; nfi < 4; ++nfi)
            mma_bf16(d[nfi], ah0, ah1, ah2, ah0, bl0[nfi], bl1[nfi]);
        #pragma unroll
        for (int nfi = 0; nfi < 4; ++nfi)
            mma_bf16(d[nfi], al0, al1, al2, al0, bh0[nfi], bh1[nfi]);
    }

    // -- epilogue: D[m,n] -> out[rb + n, col0 + m] ------------------------------
    #pragma unroll
    for (int nfi = 0; nfi < 4; ++nfi) {
        const size_t n0 = (size_t)(rb + nfi * 8 + 2 * t) * L_LEN;
        out[n0 + mg]             = d[nfi][0];
        out[n0 + L_LEN + mg]     = d[nfi][1];
        out[n0 + mg + 8]         = d[nfi][2];
        out[n0 + L_LEN + mg + 8] = d[nfi][3];
    }
}

extern "C" void kernel_launch(void* const* d_in, const int* in_sizes, int n_in,
                              void* d_out, int out_size) {
    const float* x  = (const float*)d_in[0];   // [64, 65536] fp32
    const float* tw = (const float*)d_in[1];   // [4] fp32
    float* out = (float*)d_out;

    cudaFuncSetAttribute(hann_mma_kernel,
                         cudaFuncAttributeMaxDynamicSharedMemorySize, SM_TOTAL);
    dim3 grid(L_LEN / TILE_M, 64 / ROWS);      // (512, 2) = 1024 CTAs
    hann_mma_kernel<<<grid, THREADS, SM_TOTAL>>>(x, tw, out);
}